// round 1
// baseline (speedup 1.0000x reference)
#include <cuda_runtime.h>
#include <cuda_bf16.h>
#include <math.h>

// Problem constants (from reference): z is (Kn=4, M=128, D=64, T=256)
#define Tn    256
#define NMID  254          // T-2 middle points
#define ND    64           // D
#define NKM   512          // Kn*M
#define BW    9            // band storage width (half-bandwidth 8 + diag)
#define NPAD  272          // padded Sigma rows for the register-window recursion
#define NBLK  29           // 29*9 = 261 >= 254 recursion steps
#define EPSv  1e-5f

// Scratch (device globals: no allocation allowed)
__device__ float g_Lb[ND][NMID * BW];   // banded L: g_Lb[d][i*9+c] = L[i][i-c]
__device__ float g_A0[ND][NMID];        // A_mu[:, 0]
__device__ float g_A1[ND][NMID];        // A_mu[:, 1]
__device__ float g_pld[ND];             // per-d partial logdet

// ---------------------------------------------------------------------------
// Setup kernel: one block (1 warp) per d.
//  1) compute K_predEP / A_mu, store A_mu to global
//  2) build banded Sigma in smem (parallel across lanes)
//  3) banded Cholesky: all 32 lanes redundantly run a register-resident
//     9x9 circular-window recursion (zero inter-lane communication);
//     lane c writes the finalized column entry for band offset c.
// ---------------------------------------------------------------------------
__global__ __launch_bounds__(32) void setup_kernel(const float* __restrict__ log_tau) {
    const int d = blockIdx.x;
    const int lane = threadIdx.x;

    __shared__ float Kp0[NMID], Kp1[NMID], A0s[NMID], A1s[NMID];
    __shared__ float Sb[NPAD][BW];

    const float tau = expf(log_tau[d]);
    const float h = 1.0f / (2.0f * tau * tau);        // (T_S*lag)^2/(2 tau^2), T_S=1
    const float r255 = expf(-h * 255.0f * 255.0f);    // K(0, T-1)
    const float idet = 1.0f / (1.0f - r255 * r255);

    for (int i = lane; i < NMID; i += 32) {
        float x0 = (float)(i + 1);        // lag to t=0
        float x1 = (float)(254 - i);      // lag to t=T-1
        float k0 = expf(-h * x0 * x0);
        float k1 = expf(-h * x1 * x1);
        Kp0[i] = k0;
        Kp1[i] = k1;
        float a0 = idet * (k0 - r255 * k1);
        float a1 = idet * (k1 - r255 * k0);
        A0s[i] = a0;
        A1s[i] = a1;
        g_A0[d][i] = a0;
        g_A1[d][i] = a1;
    }
    __syncwarp();

    // Banded Sigma: Sb[i][c] = Sigma[i][i-c] (0 outside, dummy identity rows past NMID)
    for (int idx = lane; idx < NPAD * BW; idx += 32) {
        int i = idx / BW;
        int c = idx - i * BW;
        float v = 0.0f;
        if (i < NMID) {
            if (c <= i) {
                float gc = expf(-h * (float)(c * c));
                v = gc - A0s[i] * Kp0[i - c] - A1s[i] * Kp1[i - c];
                if (c == 0) v += EPSv;
            }
        } else {
            v = (c == 0) ? 1.0f : 0.0f;
        }
        Sb[i][c] = v;
    }
    __syncwarp();

    // Register-window banded Cholesky (right-looking).
    float W[9][9];
#pragma unroll
    for (int s = 0; s < 9; ++s)
#pragma unroll
        for (int c = 0; c < 9; ++c)
            W[s][c] = Sb[s][c];

    float prod = 1.0f;
    int j = 0;
    float* __restrict__ Ld = g_Lb[d];

    for (int blk = 0; blk < NBLK; ++blk) {
#pragma unroll
        for (int s = 0; s < 9; ++s) {
            float x = W[s][0];
            float dg = sqrtf(x);
            float inv = 1.0f / dg;

            float l[9];
            l[0] = dg;
#pragma unroll
            for (int c = 1; c < 9; ++c)
                l[c] = W[(s + c) % 9][c] * inv;

            // finalized column j: lane c writes L[j+c][j] = Lb[j+c][c]
#pragma unroll
            for (int c = 0; c < 9; ++c)
                if (lane == c && j + c < NMID)
                    Ld[(j + c) * BW + c] = l[c];

            // rank-1 update of trailing window
#pragma unroll
            for (int r1 = 1; r1 < 9; ++r1)
#pragma unroll
                for (int r2 = 1; r2 <= r1; ++r2)
                    W[(s + r1) % 9][r1 - r2] -= l[r1] * l[r2];

            // refill slot s with Sigma row j+9
            {
                const float* src = Sb[j + 9];
#pragma unroll
                for (int c = 0; c < 9; ++c)
                    W[s][c] = src[c];
            }

            if (j < NMID) prod *= dg;
            ++j;
        }
    }

    if (lane == 0) g_pld[d] = logf(prod);
}

// ---------------------------------------------------------------------------
// Apply kernel: z_out = [z0 | A_mu z_EP + L z_mid | zT-1], banded 9-tap matvec.
// Grid (64, 8): block = (d, chunk of 64 batch rows). L row per thread is
// loaded to REGISTERS once (thread t's output index is fixed across rows).
// ---------------------------------------------------------------------------
__global__ __launch_bounds__(256) void apply_kernel(const float* __restrict__ z,
                                                    const float* __restrict__ sldj,
                                                    float* __restrict__ out,
                                                    int osize) {
    const int d = blockIdx.x;
    const int chunk = blockIdx.y;
    const int t = threadIdx.x;

    __shared__ float Ls[NMID * BW];
    __shared__ float A0s[NMID], A1s[NMID];

    for (int idx = t; idx < NMID * BW; idx += 256) Ls[idx] = g_Lb[d][idx];
    for (int idx = t; idx < NMID; idx += 256) {
        A0s[idx] = g_A0[d][idx];
        A1s[idx] = g_A1[d][idx];
    }

    // Deterministic scalar output (single thread, fixed order; no atomics)
    if (d == 0 && chunk == 0 && t == 0) {
        float s = sldj[0];
        for (int dd = 0; dd < ND; ++dd) s += g_pld[dd];
        out[osize - 1] = s;
    }
    __syncthreads();

    const bool mid = (t >= 1 && t <= 254);
    const int i = t - 1;
    float Lr[9];
    float a0 = 0.0f, a1 = 0.0f;
    if (mid) {
        a0 = A0s[i];
        a1 = A1s[i];
#pragma unroll
        for (int c = 0; c < 9; ++c)
            Lr[c] = (c <= i) ? Ls[i * BW + c] : 0.0f;
    }

    for (int r = 0; r < 64; ++r) {
        int km = chunk * 64 + r;
        const float* __restrict__ zr = z + ((size_t)(km * ND + d)) * Tn;
        float val;
        if (!mid) {
            val = zr[t];                 // endpoints pass through
        } else {
            float z0 = zr[0];
            float zE = zr[255];
            float acc = a0 * z0 + a1 * zE;
#pragma unroll
            for (int c = 0; c < 9; ++c)
                if (c <= i)              // guard also prevents OOB z reads
                    acc += Lr[c] * zr[t - c];
            val = acc;
        }
        out[((size_t)(km * ND + d)) * Tn + t] = val;
    }
}

// ---------------------------------------------------------------------------
// Inputs (metadata order): z (4*128*64*256 f32), sum_log_det_jacobians (1 f32),
// log_tau (64 f32). Output: z_out flattened (8388608) followed by scalar.
// ---------------------------------------------------------------------------
extern "C" void kernel_launch(void* const* d_in, const int* in_sizes, int n_in,
                              void* d_out, int out_size) {
    const float* z = (const float*)d_in[0];
    const float* sldj = (const float*)d_in[1];
    const float* log_tau = (const float*)d_in[2];
    float* out = (float*)d_out;

    setup_kernel<<<ND, 32>>>(log_tau);
    apply_kernel<<<dim3(ND, 8), 256>>>(z, sldj, out, out_size);
}

// round 3
// speedup vs baseline: 2.1084x; 2.1084x over previous
#include <cuda_runtime.h>
#include <cuda_bf16.h>
#include <math.h>

// z is (Kn=4, M=128, D=64, T=256)
#define Tn    256
#define NMID  254
#define ND    64
#define NKM   512
#define BW    9
#define NPAD  272
#define NSTEP 261          // 29*9 recursion steps (padded past NMID)
#define JUMPJ 234          // 26*9: resume point after Toeplitz skip
#define EPSv  1e-5f

__device__ float g_Lb[ND][NMID * BW];   // banded L: g_Lb[d][i*9+c] = L[i][i-c]
__device__ float g_A0[ND][NMID];
__device__ float g_A1[ND][NMID];
__device__ float g_pld[ND];

// ---------------------------------------------------------------------------
// Setup: one warp per d. Banded register-window Cholesky with Toeplitz
// convergence jump. FIX vs R2: the skip fill is COLUMN-wise — for each
// skipped column jc it writes Ld[(jc+c)*BW+c] = stencil[c], exactly the
// entries the recursion would have produced (including rows >= JUMPJ owned
// by skipped columns). Resumed columns (>= JUMPJ) write disjoint entries.
// ---------------------------------------------------------------------------
__global__ __launch_bounds__(32) void setup_kernel(const float* __restrict__ log_tau) {
    const int d = blockIdx.x;
    const int lane = threadIdx.x;

    __shared__ float Kp0[NMID], Kp1[NMID], A0s[NMID], A1s[NMID];
    __shared__ float Sb[NPAD][BW];
    __shared__ float stc[BW];

    const float tau = expf(log_tau[d]);
    const float h = 1.0f / (2.0f * tau * tau);
    const float r255 = expf(-h * 255.0f * 255.0f);
    const float idet = 1.0f / (1.0f - r255 * r255);

    for (int i = lane; i < NMID; i += 32) {
        float x0 = (float)(i + 1);
        float x1 = (float)(254 - i);
        float k0 = expf(-h * x0 * x0);
        float k1 = expf(-h * x1 * x1);
        Kp0[i] = k0; Kp1[i] = k1;
        float a0 = idet * (k0 - r255 * k1);
        float a1 = idet * (k1 - r255 * k0);
        A0s[i] = a0; A1s[i] = a1;
        g_A0[d][i] = a0; g_A1[d][i] = a1;
    }
    __syncwarp();

    for (int idx = lane; idx < NPAD * BW; idx += 32) {
        int i = idx / BW;
        int c = idx - i * BW;
        float v = 0.0f;
        if (i < NMID) {
            if (c <= i) {
                float gc = expf(-h * (float)(c * c));
                v = gc - A0s[i] * Kp0[i - c] - A1s[i] * Kp1[i - c];
                if (c == 0) v += EPSv;
            }
        } else {
            v = (c == 0) ? 1.0f : 0.0f;
        }
        Sb[i][c] = v;
    }
    __syncwarp();

    float W[9][9];
#pragma unroll
    for (int s = 0; s < 9; ++s)
#pragma unroll
        for (int c = 0; c < 9; ++c)
            W[s][c] = Sb[s][c];

    float prod = 1.0f;
    float ld_skip = 0.0f;
    float lprev[9];
#pragma unroll
    for (int c = 0; c < 9; ++c) lprev[c] = -1.0f;
    bool conv = false, jumped = false;
    int j = 0;
    float* __restrict__ Ld = g_Lb[d];

    while (j < NSTEP) {
        // block boundary: j % 9 == 0. Jump if stationary.
        if (conv && !jumped && j <= 225) {
#pragma unroll
            for (int c = 0; c < 9; ++c)
                if (lane == c) stc[c] = lprev[c];
            __syncwarp();
            const int skip = JUMPJ - j;
            // COLUMN-wise fill: replicate exactly what the recursion writes
            for (int idx = lane; idx < skip * BW; idx += 32) {
                int jc = j + idx / BW;          // skipped column
                int c  = idx - (idx / BW) * BW; // band offset
                int r  = jc + c;                // row
                if (r < NMID)
                    Ld[r * BW + c] = stc[c];
            }
            __syncwarp();
            ld_skip = (float)skip * logf(lprev[0]);
            j = JUMPJ;
            jumped = true;
        }
#pragma unroll
        for (int s = 0; s < 9; ++s) {
            float x = W[s][0];
            float inv = rsqrtf(x);
            float dg = x * inv;

            float l[9];
            l[0] = dg;
#pragma unroll
            for (int c = 1; c < 9; ++c)
                l[c] = W[(s + c) % 9][c] * inv;

            // convergence tracking (bitwise)
            bool eq = true;
#pragma unroll
            for (int c = 0; c < 9; ++c) eq = eq && (l[c] == lprev[c]);
            if (eq && j >= 24) conv = true;
#pragma unroll
            for (int c = 0; c < 9; ++c) lprev[c] = l[c];

            // finalized column j: lane c writes L[j+c][j]
#pragma unroll
            for (int c = 0; c < 9; ++c)
                if (lane == c && j + c < NMID)
                    Ld[(j + c) * BW + c] = l[c];

            // rank-1 trailing update
#pragma unroll
            for (int r1 = 1; r1 < 9; ++r1)
#pragma unroll
                for (int r2 = 1; r2 <= r1; ++r2)
                    W[(s + r1) % 9][r1 - r2] -= l[r1] * l[r2];

            // refill slot s with Sigma row j+9
            {
                const float* src = Sb[j + 9];
#pragma unroll
                for (int c = 0; c < 9; ++c)
                    W[s][c] = src[c];
            }

            if (j < NMID) prod *= dg;
            ++j;
        }
    }

    if (lane == 0) g_pld[d] = logf(prod) + ld_skip;
}

// ---------------------------------------------------------------------------
// Apply: z_out = [z0 | A z_EP + L z_mid | zE]. Each thread owns 4 consecutive
// t (float4-aligned), keeps its 4 L-rows (9 taps) + a0/a1 in registers,
// streams rows with 3x LDG.128 + 2 broadcast LDG + 1x STG.128 per row.
// ---------------------------------------------------------------------------
__global__ __launch_bounds__(256) void apply_kernel(const float* __restrict__ z,
                                                    const float* __restrict__ sldj,
                                                    float* __restrict__ out,
                                                    int osize) {
    const int d = blockIdx.x;
    const int chunk = blockIdx.y;
    const int tid = threadIdx.x;
    const int tg = tid & 63;       // t-group: outputs t0..t0+3
    const int rs = tid >> 6;       // row slot 0..3
    const int t0 = tg << 2;

    // deterministic logdet scalar
    if (d == 0 && chunk == 0 && tid == 0) {
        float s = sldj[0];
        for (int dd = 0; dd < ND; ++dd) s += g_pld[dd];
        out[osize - 1] = s;
    }

    // Per-thread L rows i = t0+u-1, u=0..3 (registers)
    float L[4][9];
    float a0[4], a1[4];
#pragma unroll
    for (int u = 0; u < 4; ++u) {
        int i = t0 + u - 1;
        bool valid = (i >= 0) && (i < NMID);
        a0[u] = valid ? g_A0[d][i] : 0.0f;
        a1[u] = valid ? g_A1[d][i] : 0.0f;
#pragma unroll
        for (int c = 0; c < 9; ++c)
            L[u][c] = (valid && c <= i) ? g_Lb[d][i * BW + c] : 0.0f;
    }

    for (int iter = 0; iter < 16; ++iter) {
        int km = chunk * 64 + iter * 4 + rs;
        const float* __restrict__ zr = z + (size_t)(km * ND + d) * Tn;

        float4 q2 = *reinterpret_cast<const float4*>(zr + t0);
        float4 q1 = make_float4(0.f, 0.f, 0.f, 0.f);
        float4 q0 = make_float4(0.f, 0.f, 0.f, 0.f);
        if (tg >= 1) q1 = *reinterpret_cast<const float4*>(zr + t0 - 4);
        if (tg >= 2) q0 = *reinterpret_cast<const float4*>(zr + t0 - 8);

        float w[12];
        w[0] = q0.x; w[1] = q0.y; w[2] = q0.z; w[3] = q0.w;
        w[4] = q1.x; w[5] = q1.y; w[6] = q1.z; w[7] = q1.w;
        w[8] = q2.x; w[9] = q2.y; w[10] = q2.z; w[11] = q2.w;

        float z0 = zr[0];
        float zE = zr[255];

        float v[4];
#pragma unroll
        for (int u = 0; u < 4; ++u) {
            float acc = a0[u] * z0 + a1[u] * zE;
#pragma unroll
            for (int c = 0; c < 9; ++c)
                acc += L[u][c] * w[u - c + 8];
            v[u] = acc;
        }
        if (tg == 0) v[0] = z0;
        if (tg == 63) v[3] = zE;

        float4 ov = make_float4(v[0], v[1], v[2], v[3]);
        *reinterpret_cast<float4*>(out + (size_t)(km * ND + d) * Tn + t0) = ov;
    }
}

extern "C" void kernel_launch(void* const* d_in, const int* in_sizes, int n_in,
                              void* d_out, int out_size) {
    const float* z = (const float*)d_in[0];
    const float* sldj = (const float*)d_in[1];
    const float* log_tau = (const float*)d_in[2];
    float* out = (float*)d_out;

    setup_kernel<<<ND, 32>>>(log_tau);
    apply_kernel<<<dim3(ND, 8), 256>>>(z, sldj, out, out_size);
}